// round 15
// baseline (speedup 1.0000x reference)
#include <cuda_runtime.h>
#include <cuda_fp16.h>
#include <cstdint>

// Problem constants:
// B=8, H=W=128, DIM=512, NH=8, HD=64, WIN=8x8 (N=64 tok/window), SHIFT=(4,4)
// windows: 2048 ; rows M = 131072

// Scratch (device globals = sanctioned scratch)
__device__ __half g_qkvh[3u * 2048u * 8u * 64u * 64u]; // [part][win][h][t][d] fp16; q,k RoPE'd
__device__ __half g_xh [131072u * 512u];               // gathered x, fp16
__device__ __half g_oh [131072u * 512u];               // attention out, fp16
__device__ __half g_wqh[1536u * 512u];                 // qkv_w fp16
__device__ __half g_wph[512u * 512u];                  // proj_w fp16

#define L2T16 0.8304820237218406f      // log2(10000)/16

// ---------------------------------------------------------------------------
// helpers
// ---------------------------------------------------------------------------
__device__ __forceinline__ void cp16(uint32_t smem, const void* gmem) {
    asm volatile("cp.async.cg.shared.global [%0], [%1], 16;\n" :: "r"(smem), "l"(gmem));
}
__device__ __forceinline__ void mma_f16(float* c, const uint32_t* a, const uint32_t* b) {
    asm volatile(
        "mma.sync.aligned.m16n8k16.row.col.f32.f16.f16.f32 "
        "{%0,%1,%2,%3}, {%4,%5,%6,%7}, {%8,%9}, {%0,%1,%2,%3};"
        : "+f"(c[0]), "+f"(c[1]), "+f"(c[2]), "+f"(c[3])
        : "r"(a[0]), "r"(a[1]), "r"(a[2]), "r"(a[3]), "r"(b[0]), "r"(b[1]));
}
__device__ __forceinline__ uint32_t pack_h2(float v0, float v1) {
    uint32_t p;
    asm("cvt.rn.f16x2.f32 %0, %1, %2;" : "=r"(p) : "f"(v1), "f"(v0));
    return p;
}
__device__ __forceinline__ void ldsm_x4(uint32_t* d, uint32_t addr) {
    asm volatile("ldmatrix.sync.aligned.m8n8.x4.shared.b16 {%0,%1,%2,%3}, [%4];"
                 : "=r"(d[0]), "=r"(d[1]), "=r"(d[2]), "=r"(d[3]) : "r"(addr));
}

// GEMM smem geometry (BK=64): rows of 64 halves + 16B pad = 144 bytes.
#define ROWB 144
#define STAGE_B (256 * ROWB)            // A(128 rows) + B(128 rows) = 36864 B
#define SMEM_BYTES (3 * STAGE_B)        // 110592 B -> 2 CTAs/SM

// ---------------------------------------------------------------------------
// Kernel 0: prep — gather x (roll+partition) -> g_xh (fp16); weights -> fp16.
// 4 rows per CTA, 128 threads, fully coalesced.
// ---------------------------------------------------------------------------
__global__ __launch_bounds__(128) void k_prep(const float* __restrict__ x,
                                              const float* __restrict__ qkv_w,
                                              const float* __restrict__ proj_w)
{
    const int bid = blockIdx.x;
    const int tid = threadIdx.x;

#pragma unroll
    for (int it = 0; it < 4; it++) {
        int e   = tid + it * 128;       // 0..511
        int rl  = e >> 7;               // row within CTA group (0..3)
        int f4  = e & 127;              // float4 index within row

        const float* src;
        __half* dst;
        if (bid < 32768) {
            int m   = bid * 4 + rl;
            int win = m >> 6, t = m & 63;
            int b   = win >> 8;
            int wh  = (win >> 4) & 15;
            int ww  = win & 15;
            int i   = t >> 3, j = t & 7;
            int r   = (wh * 8 + i + 4) & 127;     // roll(-4) gather
            int c   = (ww * 8 + j + 4) & 127;
            src = x + ((size_t)((((b << 7) | r) << 7) | c) << 9);
            dst = g_xh + (size_t)m * 512;
        } else {
            int w = (bid - 32768) * 4 + rl;        // 0..2047
            if (w < 1536) { src = qkv_w + (size_t)w * 512;           dst = g_wqh + (size_t)w * 512; }
            else          { src = proj_w + (size_t)(w - 1536) * 512; dst = g_wph + (size_t)(w - 1536) * 512; }
        }

        float4 v = ((const float4*)src)[f4];
        uint2 o;
        o.x = pack_h2(v.x, v.y);
        o.y = pack_h2(v.z, v.w);
        ((uint2*)dst)[f4] = o;
    }
}

// ---------------------------------------------------------------------------
// fp16 GEMM core: BM=BN=128, BK=64, K=512 (8 ktiles, FULLY UNROLLED),
// 256 threads, 8 warps (4M x 2N), warp tile 32x64, m16n8k16,
// all-x4 ldmatrix fragments, 3-stage cp.async, 1 barrier per ktile.
// ---------------------------------------------------------------------------
#define GEMM_MAIN(APTR, BPTR)                                                  \
    const int q_  = lane >> 3, r_ = lane & 7;                                  \
    uint32_t aLane[2];                                                         \
    _Pragma("unroll")                                                          \
    for (int mi = 0; mi < 2; mi++)                                             \
        aLane[mi] = (uint32_t)((warpM * 32 + mi * 16 + (q_ & 1) * 8 + r_) * ROWB \
                               + (q_ >> 1) * 16);                              \
    const uint32_t bLane = (uint32_t)(128 * ROWB +                             \
        (warpN * 64 + ((lane >> 4) << 3) + r_) * ROWB + ((q_ & 1) * 16));      \
    auto loadStage = [&](int s, int k0) {                                      \
        uint32_t ab = smemBase + s * STAGE_B;                                  \
        uint32_t bb = ab + 128 * ROWB;                                         \
        _Pragma("unroll")                                                      \
        for (int it = 0; it < 4; it++) {                                       \
            int ch = tid + it * 256;          /* 0..1023 */                    \
            int row = ch >> 3, ci = ch & 7;                                    \
            cp16(ab + row * ROWB + ci * 16, APTR + (size_t)row * 512 + k0 + ci * 8); \
            cp16(bb + row * ROWB + ci * 16, BPTR + (size_t)row * 512 + k0 + ci * 8); \
        }                                                                      \
    };                                                                         \
    loadStage(0, 0);                                                           \
    asm volatile("cp.async.commit_group;\n");                                  \
    loadStage(1, 64);                                                          \
    asm volatile("cp.async.commit_group;\n");                                  \
    asm volatile("cp.async.wait_group 1;\n");                                  \
    __syncthreads();                                                           \
    _Pragma("unroll")                                                          \
    for (int kt = 0; kt < 8; kt++) {                                           \
        if (kt + 2 < 8) {                                                      \
            loadStage((kt + 2) % 3, (kt + 2) * 64);                            \
            asm volatile("cp.async.commit_group;\n");                          \
        }                                                                      \
        const uint32_t stA = smemBase + (kt % 3) * STAGE_B;                    \
        _Pragma("unroll")                                                      \
        for (int ks = 0; ks < 4; ks++) {                                       \
            uint32_t af[2][4];                                                 \
            ldsm_x4(af[0], stA + aLane[0] + ks * 32);                          \
            ldsm_x4(af[1], stA + aLane[1] + ks * 32);                          \
            _Pragma("unroll")                                                  \
            for (int ni2 = 0; ni2 < 4; ni2++) {                                \
                uint32_t bf[4];                                                \
                ldsm_x4(bf, stA + bLane + ni2 * (16 * ROWB) + ks * 32);        \
                mma_f16(acc[0][ni2 * 2 + 0], af[0], bf);                       \
                mma_f16(acc[1][ni2 * 2 + 0], af[1], bf);                       \
                mma_f16(acc[0][ni2 * 2 + 1], af[0], bf + 2);                   \
                mma_f16(acc[1][ni2 * 2 + 1], af[1], bf + 2);                   \
            }                                                                  \
        }                                                                      \
        if (kt < 7) {                                                          \
            if (kt + 2 < 8) asm volatile("cp.async.wait_group 1;\n");          \
            else            asm volatile("cp.async.wait_group 0;\n");          \
            __syncthreads();                                                   \
        }                                                                      \
    }

// ---------------------------------------------------------------------------
// Kernel 1: QKV GEMM (fp16) + bias + fused RoPE/scale + smem-staged
// fully-coalesced fp16 store into g_qkvh.  M=131072 K=512 N=1536
// ---------------------------------------------------------------------------
__global__ __launch_bounds__(256, 2) void k_qkv_gemm(const float* __restrict__ bias)
{
    extern __shared__ uint32_t sm32[];
    const uint32_t smemBase = (uint32_t)__cvta_generic_to_shared(sm32);

    const int tid   = threadIdx.x;
    const int nTile = blockIdx.x;
    const int mTile = blockIdx.y;

    const int warpId = tid >> 5, lane = tid & 31;
    const int warpM  = warpId & 3;
    const int warpN  = warpId >> 2;
    const int n0     = nTile * 128;
    const int g      = lane >> 2, t4 = lane & 3;

    float acc[2][8][4];
#pragma unroll
    for (int mi = 0; mi < 2; mi++)
#pragma unroll
        for (int ni = 0; ni < 8; ni++)
#pragma unroll
            for (int e = 0; e < 4; e++) acc[mi][ni][e] = 0.f;

    const __half* Ag = g_xh + (size_t)(mTile * 128) * 512;
    const __half* Bg = g_wqh + (size_t)n0 * 512;
    GEMM_MAIN(Ag, Bg)

    const int nbase = n0 + warpN * 64;     // 64-aligned -> one (part, head)
    const int part  = nbase >> 9;

    // bias (reference: GEMM + b, THEN rope)
#pragma unroll
    for (int ni = 0; ni < 8; ni++) {
        int n = nbase + ni * 8 + 2 * t4;
        float b0 = bias[n], b1 = bias[n + 1];
#pragma unroll
        for (int mi = 0; mi < 2; mi++) {
            acc[mi][ni][0] += b0; acc[mi][ni][1] += b1;
            acc[mi][ni][2] += b0; acc[mi][ni][3] += b1;
        }
    }

    if (part < 2) {
        const float scale = (part == 0) ? 0.125f : 1.0f;
        float invv[2][2];  // [ni&1][j]: e = (ni&1)*8 + 2*t4 + j
#pragma unroll
        for (int p = 0; p < 2; p++)
#pragma unroll
            for (int j = 0; j < 2; j++)
                invv[p][j] = exp2f(-(float)(p * 8 + 2 * t4 + j) * L2T16);

#pragma unroll
        for (int mi = 0; mi < 2; mi++) {
#pragma unroll
            for (int rr = 0; rr < 2; rr++) {
                int t = (mTile * 128 + warpM * 32 + mi * 16 + g + rr * 8) & 63;
                float posR = (float)(t >> 3), posC = (float)(t & 7);
#pragma unroll
                for (int qq = 0; qq < 4; qq++) {
                    const int niList[4] = {0, 1, 4, 5};
                    int ni = niList[qq];
                    float pos = (ni < 4) ? posR : posC;
#pragma unroll
                    for (int j = 0; j < 2; j++) {
                        float ang = pos * invv[ni & 1][j];
                        float sv, cv;
                        __sincosf(ang, &sv, &cv);
                        float a = acc[mi][ni][rr * 2 + j];
                        float b = acc[mi][ni + 2][rr * 2 + j];
                        acc[mi][ni][rr * 2 + j]     = (a * cv - b * sv) * scale;
                        acc[mi][ni + 2][rr * 2 + j] = (b * cv + a * sv) * scale;
                    }
                }
            }
        }
    }

    // ---- smem-staged coalesced store ----
    __syncthreads();    // mainloop smem dead; reuse stage region
#pragma unroll
    for (int ni = 0; ni < 8; ni++) {
#pragma unroll
        for (int mi = 0; mi < 2; mi++) {
#pragma unroll
            for (int rr = 0; rr < 2; rr++) {
                int mloc = warpM * 32 + mi * 16 + g + rr * 8;
                sm32[mloc * 72 + warpN * 32 + ni * 4 + t4] =
                    pack_h2(acc[mi][ni][rr * 2 + 0], acc[mi][ni][rr * 2 + 1]);
            }
        }
    }
    __syncthreads();

    {
        int mloc = tid >> 1, nh = tid & 1;
        int n64  = n0 + nh * 64;
        int p2   = n64 >> 9, h2 = (n64 >> 6) & 7;
        int m    = mTile * 128 + mloc, win = m >> 6, t = m & 63;
        size_t base = ((((size_t)p2 * 2048 + win) * 8 + h2) * 64 + t) * 64; // halves
        uint4* dstp = (uint4*)(g_qkvh + base);
        const uint32_t* srcp = sm32 + mloc * 72 + nh * 32;
#pragma unroll
        for (int w4 = 0; w4 < 8; w4++)
            dstp[w4] = *(const uint4*)(srcp + w4 * 4);
    }
}

// ---------------------------------------------------------------------------
// Kernel 2: per (window, head) attention, all-fp16 MMA (fp32 accum/softmax).
// V transpose uses XOR chunk swizzle; O staged through own Qs strip and
// written as 4x STG.128 per lane (full sectors).
// ---------------------------------------------------------------------------
#define ASTW 36   // words per 64-half row (32 data + 4 pad)

__global__ __launch_bounds__(128) void k_attn_f16()
{
    __shared__ uint32_t Qs[64 * ASTW];   // Q [t][d]; P then O overlay own strip
    __shared__ uint32_t Ks[64 * ASTW];   // K [t][d]
    __shared__ uint32_t Vs[64 * ASTW];   // V [d][t], chunk-swizzled

    const int tid  = threadIdx.x;
    const int warp = tid >> 5;
    const int lane = tid & 31;
    const int g    = lane >> 2;
    const int c    = lane & 3;
    const int m0   = warp * 16;

    const int win = blockIdx.x >> 3;
    const int h   = blockIdx.x & 7;

    const size_t qoff = ((size_t)win * 8 + h) * 4096;
    const size_t pstr = (size_t)2048 * 8 * 4096;
    const uint4* qg = (const uint4*)(g_qkvh + qoff);
    const uint4* kg = (const uint4*)(g_qkvh + pstr + qoff);
    const uint4* vg = (const uint4*)(g_qkvh + 2 * pstr + qoff);
    __half* VsH = (__half*)Vs;

#pragma unroll
    for (int it = 0; it < 4; it++) {
        int e4 = tid + it * 128;
        int t  = e4 >> 3;
        int ci = e4 & 7;
        *(uint4*)(Qs + t * ASTW + ci * 4) = qg[e4];
        *(uint4*)(Ks + t * ASTW + ci * 4) = kg[e4];
        uint4 w = vg[e4];
        const __half* hb = (const __half*)&w;
        int tc = (t >> 3), tl = (t & 7);
#pragma unroll
        for (int k = 0; k < 8; k++) {
            int col = ci * 8 + k;
            VsH[col * (2 * ASTW) + (((tc ^ (col >> 3)) & 7) << 3) + tl] = hb[k];
        }
    }
    __syncthreads();

    uint32_t areg[4][4];
#pragma unroll
    for (int ks = 0; ks < 4; ks++) {
        const uint32_t* ap = Qs + (m0 + g) * ASTW + ks * 8 + c;
        areg[ks][0] = ap[0];
        areg[ks][1] = ap[8 * ASTW];
        areg[ks][2] = ap[4];
        areg[ks][3] = ap[8 * ASTW + 4];
    }

    float sacc[8][4];
#pragma unroll
    for (int ni = 0; ni < 8; ni++)
#pragma unroll
        for (int e = 0; e < 4; e++) sacc[ni][e] = 0.f;

#pragma unroll
    for (int ni = 0; ni < 8; ni++) {
        const uint32_t* bb = Ks + (ni * 8 + g) * ASTW + c;
#pragma unroll
        for (int ks = 0; ks < 4; ks++) {
            uint32_t bf[2] = { bb[ks * 8], bb[ks * 8 + 4] };
            mma_f16(sacc[ni], areg[ks], bf);
        }
    }

    const bool maskOn = (((win >> 4) & 15) == 15);
    const bool warpLo = (warp < 2);

    float mx1 = -1e30f, mx2 = -1e30f;
#pragma unroll
    for (int ni = 0; ni < 8; ni++) {
        float msub = (maskOn && ((ni < 4) != warpLo)) ? 100.f : 0.f;
        sacc[ni][0] -= msub; sacc[ni][1] -= msub;
        sacc[ni][2] -= msub; sacc[ni][3] -= msub;
        mx1 = fmaxf(mx1, fmaxf(sacc[ni][0], sacc[ni][1]));
        mx2 = fmaxf(mx2, fmaxf(sacc[ni][2], sacc[ni][3]));
    }
    mx1 = fmaxf(mx1, __shfl_xor_sync(0xffffffffu, mx1, 1));
    mx1 = fmaxf(mx1, __shfl_xor_sync(0xffffffffu, mx1, 2));
    mx2 = fmaxf(mx2, __shfl_xor_sync(0xffffffffu, mx2, 1));
    mx2 = fmaxf(mx2, __shfl_xor_sync(0xffffffffu, mx2, 2));

    float s1 = 0.f, s2 = 0.f;
#pragma unroll
    for (int ni = 0; ni < 8; ni++) {
        sacc[ni][0] = __expf(sacc[ni][0] - mx1);
        sacc[ni][1] = __expf(sacc[ni][1] - mx1);
        sacc[ni][2] = __expf(sacc[ni][2] - mx2);
        sacc[ni][3] = __expf(sacc[ni][3] - mx2);
        s1 += sacc[ni][0] + sacc[ni][1];
        s2 += sacc[ni][2] + sacc[ni][3];
    }
    s1 += __shfl_xor_sync(0xffffffffu, s1, 1);
    s1 += __shfl_xor_sync(0xffffffffu, s1, 2);
    s2 += __shfl_xor_sync(0xffffffffu, s2, 1);
    s2 += __shfl_xor_sync(0xffffffffu, s2, 2);
    const float i1 = 1.f / s1, i2 = 1.f / s2;

#pragma unroll
    for (int ni = 0; ni < 8; ni++) {
        Qs[(m0 + g) * ASTW + ni * 4 + c]     = pack_h2(sacc[ni][0] * i1, sacc[ni][1] * i1);
        Qs[(m0 + g + 8) * ASTW + ni * 4 + c] = pack_h2(sacc[ni][2] * i2, sacc[ni][3] * i2);
    }
    __syncwarp();

    uint32_t preg[4][4];
#pragma unroll
    for (int ks = 0; ks < 4; ks++) {
        const uint32_t* pp = Qs + (m0 + g) * ASTW + ks * 8 + c;
        preg[ks][0] = pp[0];
        preg[ks][1] = pp[8 * ASTW];
        preg[ks][2] = pp[4];
        preg[ks][3] = pp[8 * ASTW + 4];
    }

    float oacc[8][4];
#pragma unroll
    for (int ni = 0; ni < 8; ni++)
#pragma unroll
        for (int e = 0; e < 4; e++) oacc[ni][e] = 0.f;

#pragma unroll
    for (int ni = 0; ni < 8; ni++) {
        const uint32_t* rowp = Vs + (ni * 8 + g) * ASTW;
#pragma unroll
        for (int ks = 0; ks < 4; ks++) {
            uint32_t bf[2];
            bf[0] = rowp[((((2 * ks)     ^ ni) & 7) << 2) + c];
            bf[1] = rowp[((((2 * ks + 1) ^ ni) & 7) << 2) + c];
            mma_f16(oacc[ni], preg[ks], bf);
        }
    }

    // ---- stage O in own Qs strip (P dead), then coalesced STG.128 ----
    __syncwarp();
#pragma unroll
    for (int ni = 0; ni < 8; ni++) {
        Qs[(m0 + g) * ASTW + ni * 4 + c]     = pack_h2(oacc[ni][0], oacc[ni][1]);
        Qs[(m0 + g + 8) * ASTW + ni * 4 + c] = pack_h2(oacc[ni][2], oacc[ni][3]);
    }
    __syncwarp();
    {
        int row = m0 + (lane >> 1), nh = lane & 1;
        size_t mrow = (size_t)win * 64 + row;
        uint4* dst = (uint4*)(g_oh + mrow * 512 + h * 64 + nh * 32);
        const uint32_t* srcp = Qs + row * ASTW + nh * 16;
#pragma unroll
        for (int w4 = 0; w4 < 4; w4++)
            dst[w4] = *(const uint4*)(srcp + w4 * 4);
    }
}

// ---------------------------------------------------------------------------
// Kernel 3: proj GEMM (fp16) + bias + unpartition/roll scatter.
//   M=131072 K=512 N=512   (fp32 float2 stores already fill full sectors)
// ---------------------------------------------------------------------------
__global__ __launch_bounds__(256, 2) void k_proj_gemm(const float* __restrict__ bias,
                                                      float* __restrict__ out)
{
    extern __shared__ uint32_t sm32[];
    const uint32_t smemBase = (uint32_t)__cvta_generic_to_shared(sm32);

    const int tid   = threadIdx.x;
    const int nTile = blockIdx.x;
    const int mTile = blockIdx.y;

    const int warpId = tid >> 5, lane = tid & 31;
    const int warpM  = warpId & 3;
    const int warpN  = warpId >> 2;
    const int n0     = nTile * 128;
    const int g      = lane >> 2, t4 = lane & 3;

    float acc[2][8][4];
#pragma unroll
    for (int mi = 0; mi < 2; mi++)
#pragma unroll
        for (int ni = 0; ni < 8; ni++)
#pragma unroll
            for (int e = 0; e < 4; e++) acc[mi][ni][e] = 0.f;

    const __half* Ag = g_oh + (size_t)(mTile * 128) * 512;
    const __half* Bg = g_wph + (size_t)n0 * 512;
    GEMM_MAIN(Ag, Bg)

#pragma unroll
    for (int ni = 0; ni < 8; ni++) {
        int n  = n0 + warpN * 64 + ni * 8 + 2 * t4;
        float b0 = bias[n], b1 = bias[n + 1];
#pragma unroll
        for (int mi = 0; mi < 2; mi++) {
#pragma unroll
            for (int rr2 = 0; rr2 < 2; rr2++) {
                int m   = mTile * 128 + warpM * 32 + mi * 16 + g + rr2 * 8;
                int win = m >> 6, tt = m & 63;
                int b   = win >> 8;
                int wh  = (win >> 4) & 15;
                int ww  = win & 15;
                int ii  = tt >> 3, jj = tt & 7;
                int rO  = (wh * 8 + ii + 4) & 127;
                int cO  = (ww * 8 + jj + 4) & 127;
                size_t off = ((((size_t)b << 7) | rO) << 7 | cO) << 9;
                float2 v = make_float2(acc[mi][ni][rr2 * 2 + 0] + b0,
                                       acc[mi][ni][rr2 * 2 + 1] + b1);
                *(float2*)(out + off + n) = v;
            }
        }
    }
}

// ---------------------------------------------------------------------------
extern "C" void kernel_launch(void* const* d_in, const int* in_sizes, int n_in,
                              void* d_out, int out_size)
{
    const float* x      = (const float*)d_in[0];
    const float* qkv_w  = (const float*)d_in[1];
    const float* qkv_b  = (const float*)d_in[2];
    const float* proj_w = (const float*)d_in[3];
    const float* proj_b = (const float*)d_in[4];
    float* out = (float*)d_out;

    cudaFuncSetAttribute(k_qkv_gemm,  cudaFuncAttributeMaxDynamicSharedMemorySize, SMEM_BYTES);
    cudaFuncSetAttribute(k_proj_gemm, cudaFuncAttributeMaxDynamicSharedMemorySize, SMEM_BYTES);

    k_prep<<<32768 + 512, 128>>>(x, qkv_w, proj_w);
    k_qkv_gemm<<<dim3(12, 1024), 256, SMEM_BYTES>>>(qkv_b);
    k_attn_f16<<<2048 * 8, 128>>>();
    k_proj_gemm<<<dim3(4, 1024), 256, SMEM_BYTES>>>(proj_b, out);
}

// round 16
// speedup vs baseline: 1.0350x; 1.0350x over previous
#include <cuda_runtime.h>
#include <cuda_fp16.h>
#include <cstdint>

// Problem constants:
// B=8, H=W=128, DIM=512, NH=8, HD=64, WIN=8x8 (N=64 tok/window), SHIFT=(4,4)
// windows: 2048 ; rows M = 131072

// Scratch (device globals = sanctioned scratch)
__device__ __half g_qkvh[3u * 2048u * 8u * 64u * 64u]; // [part][win][h][t][d] fp16; q,k RoPE'd
__device__ __half g_xh [131072u * 512u];               // gathered x, fp16
__device__ __half g_oh [131072u * 512u];               // attention out, fp16
__device__ __half g_wqh[1536u * 512u];                 // qkv_w fp16
__device__ __half g_wph[512u * 512u];                  // proj_w fp16

#define L2T16 0.8304820237218406f      // log2(10000)/16

// ---------------------------------------------------------------------------
// helpers
// ---------------------------------------------------------------------------
__device__ __forceinline__ void cp16(uint32_t smem, const void* gmem) {
    asm volatile("cp.async.cg.shared.global [%0], [%1], 16;\n" :: "r"(smem), "l"(gmem));
}
__device__ __forceinline__ void mma_f16(float* c, const uint32_t* a, const uint32_t* b) {
    asm volatile(
        "mma.sync.aligned.m16n8k16.row.col.f32.f16.f16.f32 "
        "{%0,%1,%2,%3}, {%4,%5,%6,%7}, {%8,%9}, {%0,%1,%2,%3};"
        : "+f"(c[0]), "+f"(c[1]), "+f"(c[2]), "+f"(c[3])
        : "r"(a[0]), "r"(a[1]), "r"(a[2]), "r"(a[3]), "r"(b[0]), "r"(b[1]));
}
__device__ __forceinline__ uint32_t pack_h2(float v0, float v1) {
    uint32_t p;
    asm("cvt.rn.f16x2.f32 %0, %1, %2;" : "=r"(p) : "f"(v1), "f"(v0));
    return p;
}
__device__ __forceinline__ void ldsm_x4(uint32_t* d, uint32_t addr) {
    asm volatile("ldmatrix.sync.aligned.m8n8.x4.shared.b16 {%0,%1,%2,%3}, [%4];"
                 : "=r"(d[0]), "=r"(d[1]), "=r"(d[2]), "=r"(d[3]) : "r"(addr));
}
__device__ __forceinline__ void ldsm_x2_trans(uint32_t* d, uint32_t addr) {
    asm volatile("ldmatrix.sync.aligned.m8n8.x2.trans.shared.b16 {%0,%1}, [%2];"
                 : "=r"(d[0]), "=r"(d[1]) : "r"(addr));
}

// GEMM smem geometry (BK=64): rows of 64 halves + 16B pad = 144 bytes.
#define ROWB 144
#define STAGE_B (256 * ROWB)            // A(128 rows) + B(128 rows) = 36864 B
#define SMEM_BYTES (3 * STAGE_B)        // 110592 B -> 2 CTAs/SM

// ---------------------------------------------------------------------------
// Kernel 0: prep — gather x (roll+partition) -> g_xh (fp16); weights -> fp16.
// 8 rows per CTA, 256 threads, fully coalesced.
// ---------------------------------------------------------------------------
__global__ __launch_bounds__(256) void k_prep(const float* __restrict__ x,
                                              const float* __restrict__ qkv_w,
                                              const float* __restrict__ proj_w)
{
    const int bid = blockIdx.x;
    const int tid = threadIdx.x;

#pragma unroll
    for (int it = 0; it < 4; it++) {
        int e   = tid + it * 256;       // 0..1023
        int rl  = e >> 7;               // row within CTA group (0..7)
        int f4  = e & 127;              // float4 index within row

        const float* src;
        __half* dst;
        if (bid < 16384) {
            int m   = bid * 8 + rl;
            int win = m >> 6, t = m & 63;
            int b   = win >> 8;
            int wh  = (win >> 4) & 15;
            int ww  = win & 15;
            int i   = t >> 3, j = t & 7;
            int r   = (wh * 8 + i + 4) & 127;     // roll(-4) gather
            int c   = (ww * 8 + j + 4) & 127;
            src = x + ((size_t)((((b << 7) | r) << 7) | c) << 9);
            dst = g_xh + (size_t)m * 512;
        } else {
            int w = (bid - 16384) * 8 + rl;        // 0..2047
            if (w < 1536) { src = qkv_w + (size_t)w * 512;           dst = g_wqh + (size_t)w * 512; }
            else          { src = proj_w + (size_t)(w - 1536) * 512; dst = g_wph + (size_t)(w - 1536) * 512; }
        }

        float4 v = ((const float4*)src)[f4];
        uint2 o;
        o.x = pack_h2(v.x, v.y);
        o.y = pack_h2(v.z, v.w);
        ((uint2*)dst)[f4] = o;
    }
}

// ---------------------------------------------------------------------------
// fp16 GEMM core: BM=BN=128, BK=64, K=512 (8 ktiles, FULLY UNROLLED),
// 256 threads, 8 warps (4M x 2N), warp tile 32x64, m16n8k16,
// all-x4 ldmatrix fragments, 3-stage cp.async, 1 barrier per ktile.
// ---------------------------------------------------------------------------
#define GEMM_MAIN(APTR, BPTR)                                                  \
    const int q_  = lane >> 3, r_ = lane & 7;                                  \
    uint32_t aLane[2];                                                         \
    _Pragma("unroll")                                                          \
    for (int mi = 0; mi < 2; mi++)                                             \
        aLane[mi] = (uint32_t)((warpM * 32 + mi * 16 + (q_ & 1) * 8 + r_) * ROWB \
                               + (q_ >> 1) * 16);                              \
    const uint32_t bLane = (uint32_t)(128 * ROWB +                             \
        (warpN * 64 + ((lane >> 4) << 3) + r_) * ROWB + ((q_ & 1) * 16));      \
    auto loadStage = [&](int s, int k0) {                                      \
        uint32_t ab = smemBase + s * STAGE_B;                                  \
        uint32_t bb = ab + 128 * ROWB;                                         \
        _Pragma("unroll")                                                      \
        for (int it = 0; it < 4; it++) {                                       \
            int ch = tid + it * 256;          /* 0..1023 */                    \
            int row = ch >> 3, ci = ch & 7;                                    \
            cp16(ab + row * ROWB + ci * 16, APTR + (size_t)row * 512 + k0 + ci * 8); \
            cp16(bb + row * ROWB + ci * 16, BPTR + (size_t)row * 512 + k0 + ci * 8); \
        }                                                                      \
    };                                                                         \
    loadStage(0, 0);                                                           \
    asm volatile("cp.async.commit_group;\n");                                  \
    loadStage(1, 64);                                                          \
    asm volatile("cp.async.commit_group;\n");                                  \
    asm volatile("cp.async.wait_group 1;\n");                                  \
    __syncthreads();                                                           \
    _Pragma("unroll")                                                          \
    for (int kt = 0; kt < 8; kt++) {                                           \
        if (kt + 2 < 8) {                                                      \
            loadStage((kt + 2) % 3, (kt + 2) * 64);                            \
            asm volatile("cp.async.commit_group;\n");                          \
        }                                                                      \
        const uint32_t stA = smemBase + (kt % 3) * STAGE_B;                    \
        _Pragma("unroll")                                                      \
        for (int ks = 0; ks < 4; ks++) {                                       \
            uint32_t af[2][4];                                                 \
            ldsm_x4(af[0], stA + aLane[0] + ks * 32);                          \
            ldsm_x4(af[1], stA + aLane[1] + ks * 32);                          \
            _Pragma("unroll")                                                  \
            for (int ni2 = 0; ni2 < 4; ni2++) {                                \
                uint32_t bf[4];                                                \
                ldsm_x4(bf, stA + bLane + ni2 * (16 * ROWB) + ks * 32);        \
                mma_f16(acc[0][ni2 * 2 + 0], af[0], bf);                       \
                mma_f16(acc[1][ni2 * 2 + 0], af[1], bf);                       \
                mma_f16(acc[0][ni2 * 2 + 1], af[0], bf + 2);                   \
                mma_f16(acc[1][ni2 * 2 + 1], af[1], bf + 2);                   \
            }                                                                  \
        }                                                                      \
        if (kt < 7) {                                                          \
            if (kt + 2 < 8) asm volatile("cp.async.wait_group 1;\n");          \
            else            asm volatile("cp.async.wait_group 0;\n");          \
            __syncthreads();                                                   \
        }                                                                      \
    }

// ---------------------------------------------------------------------------
// Kernel 1: QKV GEMM (fp16) + bias + fused RoPE/scale + fp16 pack -> g_qkvh.
//   M=131072 K=512 N=1536   (R14 epilogue — staged variant regressed)
// ---------------------------------------------------------------------------
__global__ __launch_bounds__(256, 2) void k_qkv_gemm(const float* __restrict__ bias)
{
    extern __shared__ uint32_t sm32[];
    const uint32_t smemBase = (uint32_t)__cvta_generic_to_shared(sm32);

    const int tid   = threadIdx.x;
    const int nTile = blockIdx.x;
    const int mTile = blockIdx.y;

    const int warpId = tid >> 5, lane = tid & 31;
    const int warpM  = warpId & 3;
    const int warpN  = warpId >> 2;
    const int n0     = nTile * 128;
    const int g      = lane >> 2, t4 = lane & 3;

    float acc[2][8][4];
#pragma unroll
    for (int mi = 0; mi < 2; mi++)
#pragma unroll
        for (int ni = 0; ni < 8; ni++)
#pragma unroll
            for (int e = 0; e < 4; e++) acc[mi][ni][e] = 0.f;

    const __half* Ag = g_xh + (size_t)(mTile * 128) * 512;
    const __half* Bg = g_wqh + (size_t)n0 * 512;
    GEMM_MAIN(Ag, Bg)

    const int nbase = n0 + warpN * 64;     // 64-aligned -> one (part, head)
    const int part  = nbase >> 9;
    const int h     = (nbase >> 6) & 7;

    // bias (reference: GEMM + b, THEN rope)
#pragma unroll
    for (int ni = 0; ni < 8; ni++) {
        int n = nbase + ni * 8 + 2 * t4;
        float b0 = bias[n], b1 = bias[n + 1];
#pragma unroll
        for (int mi = 0; mi < 2; mi++) {
            acc[mi][ni][0] += b0; acc[mi][ni][1] += b1;
            acc[mi][ni][2] += b0; acc[mi][ni][3] += b1;
        }
    }

    if (part < 2) {
        const float scale = (part == 0) ? 0.125f : 1.0f;
        float invv[2][2];  // [ni&1][j]: e = (ni&1)*8 + 2*t4 + j
#pragma unroll
        for (int p = 0; p < 2; p++)
#pragma unroll
            for (int j = 0; j < 2; j++)
                invv[p][j] = exp2f(-(float)(p * 8 + 2 * t4 + j) * L2T16);

#pragma unroll
        for (int mi = 0; mi < 2; mi++) {
#pragma unroll
            for (int rr = 0; rr < 2; rr++) {
                int t = (mTile * 128 + warpM * 32 + mi * 16 + g + rr * 8) & 63;
                float posR = (float)(t >> 3), posC = (float)(t & 7);
#pragma unroll
                for (int qq = 0; qq < 4; qq++) {
                    const int niList[4] = {0, 1, 4, 5};
                    int ni = niList[qq];
                    float pos = (ni < 4) ? posR : posC;
#pragma unroll
                    for (int j = 0; j < 2; j++) {
                        float ang = pos * invv[ni & 1][j];
                        float sv, cv;
                        __sincosf(ang, &sv, &cv);
                        float a = acc[mi][ni][rr * 2 + j];
                        float b = acc[mi][ni + 2][rr * 2 + j];
                        acc[mi][ni][rr * 2 + j]     = (a * cv - b * sv) * scale;
                        acc[mi][ni + 2][rr * 2 + j] = (b * cv + a * sv) * scale;
                    }
                }
            }
        }
    }

    // pack fp16 + scatter into g_qkvh[part][win][h][t][d]
    uint32_t* gq = (uint32_t*)g_qkvh;
#pragma unroll
    for (int ni = 0; ni < 8; ni++) {
        int d0 = ni * 8 + 2 * t4;          // even
#pragma unroll
        for (int mi = 0; mi < 2; mi++) {
#pragma unroll
            for (int rr = 0; rr < 2; rr++) {
                int m   = mTile * 128 + warpM * 32 + mi * 16 + g + rr * 8;
                int win = m >> 6, t = m & 63;
                size_t idx = ((((size_t)part * 2048 + win) * 8 + h) * 64 + t) * 64 + d0;
                gq[idx >> 1] = pack_h2(acc[mi][ni][rr * 2 + 0], acc[mi][ni][rr * 2 + 1]);
            }
        }
    }
}

// ---------------------------------------------------------------------------
// Kernel 2: per (window, head) attention, all-fp16 MMA (fp32 accum/softmax).
// V kept in natural [t][d] layout; PV B fragments via ldmatrix.x2.trans
// (no scalar transpose, no swizzle). ONE __syncthreads total.
// ---------------------------------------------------------------------------
#define ASTW 36   // words per 64-half row (32 data + 4 pad)

__global__ __launch_bounds__(128) void k_attn_f16()
{
    __shared__ uint32_t Qs[64 * ASTW];   // Q [t][d]; P overlays own strip
    __shared__ uint32_t Ks[64 * ASTW];   // K [t][d]
    __shared__ uint32_t Vs[64 * ASTW];   // V [t][d] natural

    const int tid  = threadIdx.x;
    const int warp = tid >> 5;
    const int lane = tid & 31;
    const int g    = lane >> 2;
    const int c    = lane & 3;
    const int m0   = warp * 16;

    const int win = blockIdx.x >> 3;
    const int h   = blockIdx.x & 7;

    const size_t qoff = ((size_t)win * 8 + h) * 4096;
    const size_t pstr = (size_t)2048 * 8 * 4096;
    const uint4* qg = (const uint4*)(g_qkvh + qoff);
    const uint4* kg = (const uint4*)(g_qkvh + pstr + qoff);
    const uint4* vg = (const uint4*)(g_qkvh + 2 * pstr + qoff);

#pragma unroll
    for (int it = 0; it < 4; it++) {
        int e4 = tid + it * 128;
        int t  = e4 >> 3;
        int ci = e4 & 7;
        *(uint4*)(Qs + t * ASTW + ci * 4) = qg[e4];
        *(uint4*)(Ks + t * ASTW + ci * 4) = kg[e4];
        *(uint4*)(Vs + t * ASTW + ci * 4) = vg[e4];
    }
    __syncthreads();

    uint32_t areg[4][4];
#pragma unroll
    for (int ks = 0; ks < 4; ks++) {
        const uint32_t* ap = Qs + (m0 + g) * ASTW + ks * 8 + c;
        areg[ks][0] = ap[0];
        areg[ks][1] = ap[8 * ASTW];
        areg[ks][2] = ap[4];
        areg[ks][3] = ap[8 * ASTW + 4];
    }

    float sacc[8][4];
#pragma unroll
    for (int ni = 0; ni < 8; ni++)
#pragma unroll
        for (int e = 0; e < 4; e++) sacc[ni][e] = 0.f;

#pragma unroll
    for (int ni = 0; ni < 8; ni++) {
        const uint32_t* bb = Ks + (ni * 8 + g) * ASTW + c;
#pragma unroll
        for (int ks = 0; ks < 4; ks++) {
            uint32_t bf[2] = { bb[ks * 8], bb[ks * 8 + 4] };
            mma_f16(sacc[ni], areg[ks], bf);
        }
    }

    const bool maskOn = (((win >> 4) & 15) == 15);
    const bool warpLo = (warp < 2);

    float mx1 = -1e30f, mx2 = -1e30f;
#pragma unroll
    for (int ni = 0; ni < 8; ni++) {
        float msub = (maskOn && ((ni < 4) != warpLo)) ? 100.f : 0.f;
        sacc[ni][0] -= msub; sacc[ni][1] -= msub;
        sacc[ni][2] -= msub; sacc[ni][3] -= msub;
        mx1 = fmaxf(mx1, fmaxf(sacc[ni][0], sacc[ni][1]));
        mx2 = fmaxf(mx2, fmaxf(sacc[ni][2], sacc[ni][3]));
    }
    mx1 = fmaxf(mx1, __shfl_xor_sync(0xffffffffu, mx1, 1));
    mx1 = fmaxf(mx1, __shfl_xor_sync(0xffffffffu, mx1, 2));
    mx2 = fmaxf(mx2, __shfl_xor_sync(0xffffffffu, mx2, 1));
    mx2 = fmaxf(mx2, __shfl_xor_sync(0xffffffffu, mx2, 2));

    float s1 = 0.f, s2 = 0.f;
#pragma unroll
    for (int ni = 0; ni < 8; ni++) {
        sacc[ni][0] = __expf(sacc[ni][0] - mx1);
        sacc[ni][1] = __expf(sacc[ni][1] - mx1);
        sacc[ni][2] = __expf(sacc[ni][2] - mx2);
        sacc[ni][3] = __expf(sacc[ni][3] - mx2);
        s1 += sacc[ni][0] + sacc[ni][1];
        s2 += sacc[ni][2] + sacc[ni][3];
    }
    s1 += __shfl_xor_sync(0xffffffffu, s1, 1);
    s1 += __shfl_xor_sync(0xffffffffu, s1, 2);
    s2 += __shfl_xor_sync(0xffffffffu, s2, 1);
    s2 += __shfl_xor_sync(0xffffffffu, s2, 2);
    const float i1 = 1.f / s1, i2 = 1.f / s2;

    // store P (fp16) into OWN 16-row strip of Qs
#pragma unroll
    for (int ni = 0; ni < 8; ni++) {
        Qs[(m0 + g) * ASTW + ni * 4 + c]     = pack_h2(sacc[ni][0] * i1, sacc[ni][1] * i1);
        Qs[(m0 + g + 8) * ASTW + ni * 4 + c] = pack_h2(sacc[ni][2] * i2, sacc[ni][3] * i2);
    }
    __syncwarp();

    uint32_t preg[4][4];
#pragma unroll
    for (int ks = 0; ks < 4; ks++) {
        const uint32_t* pp = Qs + (m0 + g) * ASTW + ks * 8 + c;
        preg[ks][0] = pp[0];
        preg[ks][1] = pp[8 * ASTW];
        preg[ks][2] = pp[4];
        preg[ks][3] = pp[8 * ASTW + 4];
    }

    float oacc[8][4];
#pragma unroll
    for (int ni = 0; ni < 8; ni++)
#pragma unroll
        for (int e = 0; e < 4; e++) oacc[ni][e] = 0.f;

    // V B-fragments via trans ldmatrix: rows t = 16ks + (lane&15), col d = ni*8
    const uint32_t vBase = (uint32_t)__cvta_generic_to_shared(Vs)
                         + (uint32_t)(lane & 15) * (ASTW * 4);
#pragma unroll
    for (int ni = 0; ni < 8; ni++) {
#pragma unroll
        for (int ks = 0; ks < 4; ks++) {
            uint32_t bf[2];
            ldsm_x2_trans(bf, vBase + (uint32_t)(ks * 16 * (ASTW * 4) + ni * 16));
            mma_f16(oacc[ni], preg[ks], bf);
        }
    }

    uint32_t* goh = (uint32_t*)g_oh;
    const size_t mrow1 = (size_t)win * 64 + m0 + g;
    const size_t mrow2 = mrow1 + 8;
#pragma unroll
    for (int ni = 0; ni < 8; ni++) {
        int d0 = h * 64 + ni * 8 + 2 * c;
        goh[(mrow1 * 512 + d0) >> 1] = pack_h2(oacc[ni][0], oacc[ni][1]);
        goh[(mrow2 * 512 + d0) >> 1] = pack_h2(oacc[ni][2], oacc[ni][3]);
    }
}

// ---------------------------------------------------------------------------
// Kernel 3: proj GEMM (fp16) + bias + unpartition/roll scatter.
//   M=131072 K=512 N=512
// ---------------------------------------------------------------------------
__global__ __launch_bounds__(256, 2) void k_proj_gemm(const float* __restrict__ bias,
                                                      float* __restrict__ out)
{
    extern __shared__ uint32_t sm32[];
    const uint32_t smemBase = (uint32_t)__cvta_generic_to_shared(sm32);

    const int tid   = threadIdx.x;
    const int nTile = blockIdx.x;
    const int mTile = blockIdx.y;

    const int warpId = tid >> 5, lane = tid & 31;
    const int warpM  = warpId & 3;
    const int warpN  = warpId >> 2;
    const int n0     = nTile * 128;
    const int g      = lane >> 2, t4 = lane & 3;

    float acc[2][8][4];
#pragma unroll
    for (int mi = 0; mi < 2; mi++)
#pragma unroll
        for (int ni = 0; ni < 8; ni++)
#pragma unroll
            for (int e = 0; e < 4; e++) acc[mi][ni][e] = 0.f;

    const __half* Ag = g_oh + (size_t)(mTile * 128) * 512;
    const __half* Bg = g_wph + (size_t)n0 * 512;
    GEMM_MAIN(Ag, Bg)

#pragma unroll
    for (int ni = 0; ni < 8; ni++) {
        int n  = n0 + warpN * 64 + ni * 8 + 2 * t4;
        float b0 = bias[n], b1 = bias[n + 1];
#pragma unroll
        for (int mi = 0; mi < 2; mi++) {
#pragma unroll
            for (int rr2 = 0; rr2 < 2; rr2++) {
                int m   = mTile * 128 + warpM * 32 + mi * 16 + g + rr2 * 8;
                int win = m >> 6, tt = m & 63;
                int b   = win >> 8;
                int wh  = (win >> 4) & 15;
                int ww  = win & 15;
                int ii  = tt >> 3, jj = tt & 7;
                int rO  = (wh * 8 + ii + 4) & 127;
                int cO  = (ww * 8 + jj + 4) & 127;
                size_t off = ((((size_t)b << 7) | rO) << 7 | cO) << 9;
                float2 v = make_float2(acc[mi][ni][rr2 * 2 + 0] + b0,
                                       acc[mi][ni][rr2 * 2 + 1] + b1);
                *(float2*)(out + off + n) = v;
            }
        }
    }
}

// ---------------------------------------------------------------------------
extern "C" void kernel_launch(void* const* d_in, const int* in_sizes, int n_in,
                              void* d_out, int out_size)
{
    const float* x      = (const float*)d_in[0];
    const float* qkv_w  = (const float*)d_in[1];
    const float* qkv_b  = (const float*)d_in[2];
    const float* proj_w = (const float*)d_in[3];
    const float* proj_b = (const float*)d_in[4];
    float* out = (float*)d_out;

    cudaFuncSetAttribute(k_qkv_gemm,  cudaFuncAttributeMaxDynamicSharedMemorySize, SMEM_BYTES);
    cudaFuncSetAttribute(k_proj_gemm, cudaFuncAttributeMaxDynamicSharedMemorySize, SMEM_BYTES);

    k_prep<<<16384 + 256, 256>>>(x, qkv_w, proj_w);
    k_qkv_gemm<<<dim3(12, 1024), 256, SMEM_BYTES>>>(qkv_b);
    k_attn_f16<<<2048 * 8, 128>>>();
    k_proj_gemm<<<dim3(4, 1024), 256, SMEM_BYTES>>>(proj_b, out);
}

// round 17
// speedup vs baseline: 1.0522x; 1.0166x over previous
#include <cuda_runtime.h>
#include <cuda_fp16.h>
#include <cstdint>

// Problem constants:
// B=8, H=W=128, DIM=512, NH=8, HD=64, WIN=8x8 (N=64 tok/window), SHIFT=(4,4)
// windows: 2048 ; rows M = 131072

// Scratch (device globals = sanctioned scratch)
__device__ __half g_qkvh[3u * 2048u * 8u * 64u * 64u]; // [part][win][h][t][d] fp16; q,k RoPE'd
__device__ __half g_xh [131072u * 512u];               // gathered x, fp16
__device__ __half g_oh [131072u * 512u];               // attention out, fp16
__device__ __half g_wqh[1536u * 512u];                 // qkv_w fp16
__device__ __half g_wph[512u * 512u];                  // proj_w fp16

#define L2T16 0.8304820237218406f      // log2(10000)/16

// ---------------------------------------------------------------------------
// helpers
// ---------------------------------------------------------------------------
__device__ __forceinline__ void cp16(uint32_t smem, const void* gmem) {
    asm volatile("cp.async.cg.shared.global [%0], [%1], 16;\n" :: "r"(smem), "l"(gmem));
}
__device__ __forceinline__ void mma_f16(float* c, const uint32_t* a, const uint32_t* b) {
    asm volatile(
        "mma.sync.aligned.m16n8k16.row.col.f32.f16.f16.f32 "
        "{%0,%1,%2,%3}, {%4,%5,%6,%7}, {%8,%9}, {%0,%1,%2,%3};"
        : "+f"(c[0]), "+f"(c[1]), "+f"(c[2]), "+f"(c[3])
        : "r"(a[0]), "r"(a[1]), "r"(a[2]), "r"(a[3]), "r"(b[0]), "r"(b[1]));
}
__device__ __forceinline__ uint32_t pack_h2(float v0, float v1) {
    uint32_t p;
    asm("cvt.rn.f16x2.f32 %0, %1, %2;" : "=r"(p) : "f"(v1), "f"(v0));
    return p;
}
__device__ __forceinline__ void ldsm_x4(uint32_t* d, uint32_t addr) {
    asm volatile("ldmatrix.sync.aligned.m8n8.x4.shared.b16 {%0,%1,%2,%3}, [%4];"
                 : "=r"(d[0]), "=r"(d[1]), "=r"(d[2]), "=r"(d[3]) : "r"(addr));
}

// GEMM smem geometry (BK=64): rows of 64 halves + 16B pad = 144 bytes.
#define ROWB 144
#define STAGE_B (256 * ROWB)            // A(128 rows) + B(128 rows) = 36864 B
#define SMEM_BYTES (3 * STAGE_B)        // 110592 B -> 2 CTAs/SM

// ---------------------------------------------------------------------------
// Kernel 0: prep — gather x (roll+partition) -> g_xh (fp16); weights -> fp16.
// 8 rows per CTA, 256 threads, fully coalesced.
// ---------------------------------------------------------------------------
__global__ __launch_bounds__(256) void k_prep(const float* __restrict__ x,
                                              const float* __restrict__ qkv_w,
                                              const float* __restrict__ proj_w)
{
    const int bid = blockIdx.x;
    const int tid = threadIdx.x;

#pragma unroll
    for (int it = 0; it < 4; it++) {
        int e   = tid + it * 256;       // 0..1023
        int rl  = e >> 7;               // row within CTA group (0..7)
        int f4  = e & 127;              // float4 index within row

        const float* src;
        __half* dst;
        if (bid < 16384) {
            int m   = bid * 8 + rl;
            int win = m >> 6, t = m & 63;
            int b   = win >> 8;
            int wh  = (win >> 4) & 15;
            int ww  = win & 15;
            int i   = t >> 3, j = t & 7;
            int r   = (wh * 8 + i + 4) & 127;     // roll(-4) gather
            int c   = (ww * 8 + j + 4) & 127;
            src = x + ((size_t)((((b << 7) | r) << 7) | c) << 9);
            dst = g_xh + (size_t)m * 512;
        } else {
            int w = (bid - 16384) * 8 + rl;        // 0..2047
            if (w < 1536) { src = qkv_w + (size_t)w * 512;           dst = g_wqh + (size_t)w * 512; }
            else          { src = proj_w + (size_t)(w - 1536) * 512; dst = g_wph + (size_t)(w - 1536) * 512; }
        }

        float4 v = ((const float4*)src)[f4];
        uint2 o;
        o.x = pack_h2(v.x, v.y);
        o.y = pack_h2(v.z, v.w);
        ((uint2*)dst)[f4] = o;
    }
}

// ---------------------------------------------------------------------------
// fp16 GEMM core: BM=BN=128, BK=64, K=512 (8 ktiles, FULLY UNROLLED),
// 256 threads, 8 warps (4M x 2N), warp tile 32x64, m16n8k16,
// all-x4 ldmatrix fragments, 3-stage cp.async, 1 barrier per ktile.
// ---------------------------------------------------------------------------
#define GEMM_MAIN(APTR, BPTR)                                                  \
    const int q_  = lane >> 3, r_ = lane & 7;                                  \
    uint32_t aLane[2];                                                         \
    _Pragma("unroll")                                                          \
    for (int mi = 0; mi < 2; mi++)                                             \
        aLane[mi] = (uint32_t)((warpM * 32 + mi * 16 + (q_ & 1) * 8 + r_) * ROWB \
                               + (q_ >> 1) * 16);                              \
    const uint32_t bLane = (uint32_t)(128 * ROWB +                             \
        (warpN * 64 + ((lane >> 4) << 3) + r_) * ROWB + ((q_ & 1) * 16));      \
    auto loadStage = [&](int s, int k0) {                                      \
        uint32_t ab = smemBase + s * STAGE_B;                                  \
        uint32_t bb = ab + 128 * ROWB;                                         \
        _Pragma("unroll")                                                      \
        for (int it = 0; it < 4; it++) {                                       \
            int ch = tid + it * 256;          /* 0..1023 */                    \
            int row = ch >> 3, ci = ch & 7;                                    \
            cp16(ab + row * ROWB + ci * 16, APTR + (size_t)row * 512 + k0 + ci * 8); \
            cp16(bb + row * ROWB + ci * 16, BPTR + (size_t)row * 512 + k0 + ci * 8); \
        }                                                                      \
    };                                                                         \
    loadStage(0, 0);                                                           \
    asm volatile("cp.async.commit_group;\n");                                  \
    loadStage(1, 64);                                                          \
    asm volatile("cp.async.commit_group;\n");                                  \
    asm volatile("cp.async.wait_group 1;\n");                                  \
    __syncthreads();                                                           \
    _Pragma("unroll")                                                          \
    for (int kt = 0; kt < 8; kt++) {                                           \
        if (kt + 2 < 8) {                                                      \
            loadStage((kt + 2) % 3, (kt + 2) * 64);                            \
            asm volatile("cp.async.commit_group;\n");                          \
        }                                                                      \
        const uint32_t stA = smemBase + (kt % 3) * STAGE_B;                    \
        _Pragma("unroll")                                                      \
        for (int ks = 0; ks < 4; ks++) {                                       \
            uint32_t af[2][4];                                                 \
            ldsm_x4(af[0], stA + aLane[0] + ks * 32);                          \
            ldsm_x4(af[1], stA + aLane[1] + ks * 32);                          \
            _Pragma("unroll")                                                  \
            for (int ni2 = 0; ni2 < 4; ni2++) {                                \
                uint32_t bf[4];                                                \
                ldsm_x4(bf, stA + bLane + ni2 * (16 * ROWB) + ks * 32);        \
                mma_f16(acc[0][ni2 * 2 + 0], af[0], bf);                       \
                mma_f16(acc[1][ni2 * 2 + 0], af[1], bf);                       \
                mma_f16(acc[0][ni2 * 2 + 1], af[0], bf + 2);                   \
                mma_f16(acc[1][ni2 * 2 + 1], af[1], bf + 2);                   \
            }                                                                  \
        }                                                                      \
        if (kt < 7) {                                                          \
            if (kt + 2 < 8) asm volatile("cp.async.wait_group 1;\n");          \
            else            asm volatile("cp.async.wait_group 0;\n");          \
            __syncthreads();                                                   \
        }                                                                      \
    }

// ---------------------------------------------------------------------------
// Kernel 1: QKV GEMM (fp16) + bias + fused RoPE/scale + fp16 pack -> g_qkvh.
//   M=131072 K=512 N=1536   (R14 epilogue)
// ---------------------------------------------------------------------------
__global__ __launch_bounds__(256, 2) void k_qkv_gemm(const float* __restrict__ bias)
{
    extern __shared__ uint32_t sm32[];
    const uint32_t smemBase = (uint32_t)__cvta_generic_to_shared(sm32);

    const int tid   = threadIdx.x;
    const int nTile = blockIdx.x;
    const int mTile = blockIdx.y;

    const int warpId = tid >> 5, lane = tid & 31;
    const int warpM  = warpId & 3;
    const int warpN  = warpId >> 2;
    const int n0     = nTile * 128;
    const int g      = lane >> 2, t4 = lane & 3;

    float acc[2][8][4];
#pragma unroll
    for (int mi = 0; mi < 2; mi++)
#pragma unroll
        for (int ni = 0; ni < 8; ni++)
#pragma unroll
            for (int e = 0; e < 4; e++) acc[mi][ni][e] = 0.f;

    const __half* Ag = g_xh + (size_t)(mTile * 128) * 512;
    const __half* Bg = g_wqh + (size_t)n0 * 512;
    GEMM_MAIN(Ag, Bg)

    const int nbase = n0 + warpN * 64;     // 64-aligned -> one (part, head)
    const int part  = nbase >> 9;
    const int h     = (nbase >> 6) & 7;

    // bias (reference: GEMM + b, THEN rope)
#pragma unroll
    for (int ni = 0; ni < 8; ni++) {
        int n = nbase + ni * 8 + 2 * t4;
        float b0 = bias[n], b1 = bias[n + 1];
#pragma unroll
        for (int mi = 0; mi < 2; mi++) {
            acc[mi][ni][0] += b0; acc[mi][ni][1] += b1;
            acc[mi][ni][2] += b0; acc[mi][ni][3] += b1;
        }
    }

    if (part < 2) {
        const float scale = (part == 0) ? 0.125f : 1.0f;
        float invv[2][2];  // [ni&1][j]: e = (ni&1)*8 + 2*t4 + j
#pragma unroll
        for (int p = 0; p < 2; p++)
#pragma unroll
            for (int j = 0; j < 2; j++)
                invv[p][j] = exp2f(-(float)(p * 8 + 2 * t4 + j) * L2T16);

#pragma unroll
        for (int mi = 0; mi < 2; mi++) {
#pragma unroll
            for (int rr = 0; rr < 2; rr++) {
                int t = (mTile * 128 + warpM * 32 + mi * 16 + g + rr * 8) & 63;
                float posR = (float)(t >> 3), posC = (float)(t & 7);
#pragma unroll
                for (int qq = 0; qq < 4; qq++) {
                    const int niList[4] = {0, 1, 4, 5};
                    int ni = niList[qq];
                    float pos = (ni < 4) ? posR : posC;
#pragma unroll
                    for (int j = 0; j < 2; j++) {
                        float ang = pos * invv[ni & 1][j];
                        float sv, cv;
                        __sincosf(ang, &sv, &cv);
                        float a = acc[mi][ni][rr * 2 + j];
                        float b = acc[mi][ni + 2][rr * 2 + j];
                        acc[mi][ni][rr * 2 + j]     = (a * cv - b * sv) * scale;
                        acc[mi][ni + 2][rr * 2 + j] = (b * cv + a * sv) * scale;
                    }
                }
            }
        }
    }

    // pack fp16 + scatter into g_qkvh[part][win][h][t][d]
    uint32_t* gq = (uint32_t*)g_qkvh;
#pragma unroll
    for (int ni = 0; ni < 8; ni++) {
        int d0 = ni * 8 + 2 * t4;          // even
#pragma unroll
        for (int mi = 0; mi < 2; mi++) {
#pragma unroll
            for (int rr = 0; rr < 2; rr++) {
                int m   = mTile * 128 + warpM * 32 + mi * 16 + g + rr * 8;
                int win = m >> 6, t = m & 63;
                size_t idx = ((((size_t)part * 2048 + win) * 8 + h) * 64 + t) * 64 + d0;
                gq[idx >> 1] = pack_h2(acc[mi][ni][rr * 2 + 0], acc[mi][ni][rr * 2 + 1]);
            }
        }
    }
}

// ---------------------------------------------------------------------------
// Kernel 2: per (window, head) attention, all-fp16 MMA (fp32 accum/softmax).
// R14 version: V transpose with XOR chunk swizzle (conflict-free STS + LDS).
// ---------------------------------------------------------------------------
#define ASTW 36   // words per 64-half row (32 data + 4 pad)

__global__ __launch_bounds__(128) void k_attn_f16()
{
    __shared__ uint32_t Qs[64 * ASTW];   // Q [t][d]; P overlays own strip
    __shared__ uint32_t Ks[64 * ASTW];   // K [t][d]
    __shared__ uint32_t Vs[64 * ASTW];   // V [d][t], chunk-swizzled

    const int tid  = threadIdx.x;
    const int warp = tid >> 5;
    const int lane = tid & 31;
    const int g    = lane >> 2;
    const int c    = lane & 3;
    const int m0   = warp * 16;

    const int win = blockIdx.x >> 3;
    const int h   = blockIdx.x & 7;

    const size_t qoff = ((size_t)win * 8 + h) * 4096;
    const size_t pstr = (size_t)2048 * 8 * 4096;
    const uint4* qg = (const uint4*)(g_qkvh + qoff);
    const uint4* kg = (const uint4*)(g_qkvh + pstr + qoff);
    const uint4* vg = (const uint4*)(g_qkvh + 2 * pstr + qoff);
    __half* VsH = (__half*)Vs;

#pragma unroll
    for (int it = 0; it < 4; it++) {
        int e4 = tid + it * 128;
        int t  = e4 >> 3;
        int ci = e4 & 7;
        *(uint4*)(Qs + t * ASTW + ci * 4) = qg[e4];
        *(uint4*)(Ks + t * ASTW + ci * 4) = kg[e4];
        uint4 w = vg[e4];
        const __half* hb = (const __half*)&w;
        int tc = (t >> 3), tl = (t & 7);
#pragma unroll
        for (int k = 0; k < 8; k++) {
            int col = ci * 8 + k;
            VsH[col * (2 * ASTW) + (((tc ^ (col >> 3)) & 7) << 3) + tl] = hb[k];
        }
    }
    __syncthreads();

    uint32_t areg[4][4];
#pragma unroll
    for (int ks = 0; ks < 4; ks++) {
        const uint32_t* ap = Qs + (m0 + g) * ASTW + ks * 8 + c;
        areg[ks][0] = ap[0];
        areg[ks][1] = ap[8 * ASTW];
        areg[ks][2] = ap[4];
        areg[ks][3] = ap[8 * ASTW + 4];
    }

    float sacc[8][4];
#pragma unroll
    for (int ni = 0; ni < 8; ni++)
#pragma unroll
        for (int e = 0; e < 4; e++) sacc[ni][e] = 0.f;

#pragma unroll
    for (int ni = 0; ni < 8; ni++) {
        const uint32_t* bb = Ks + (ni * 8 + g) * ASTW + c;
#pragma unroll
        for (int ks = 0; ks < 4; ks++) {
            uint32_t bf[2] = { bb[ks * 8], bb[ks * 8 + 4] };
            mma_f16(sacc[ni], areg[ks], bf);
        }
    }

    const bool maskOn = (((win >> 4) & 15) == 15);
    const bool warpLo = (warp < 2);

    float mx1 = -1e30f, mx2 = -1e30f;
#pragma unroll
    for (int ni = 0; ni < 8; ni++) {
        float msub = (maskOn && ((ni < 4) != warpLo)) ? 100.f : 0.f;
        sacc[ni][0] -= msub; sacc[ni][1] -= msub;
        sacc[ni][2] -= msub; sacc[ni][3] -= msub;
        mx1 = fmaxf(mx1, fmaxf(sacc[ni][0], sacc[ni][1]));
        mx2 = fmaxf(mx2, fmaxf(sacc[ni][2], sacc[ni][3]));
    }
    mx1 = fmaxf(mx1, __shfl_xor_sync(0xffffffffu, mx1, 1));
    mx1 = fmaxf(mx1, __shfl_xor_sync(0xffffffffu, mx1, 2));
    mx2 = fmaxf(mx2, __shfl_xor_sync(0xffffffffu, mx2, 1));
    mx2 = fmaxf(mx2, __shfl_xor_sync(0xffffffffu, mx2, 2));

    float s1 = 0.f, s2 = 0.f;
#pragma unroll
    for (int ni = 0; ni < 8; ni++) {
        sacc[ni][0] = __expf(sacc[ni][0] - mx1);
        sacc[ni][1] = __expf(sacc[ni][1] - mx1);
        sacc[ni][2] = __expf(sacc[ni][2] - mx2);
        sacc[ni][3] = __expf(sacc[ni][3] - mx2);
        s1 += sacc[ni][0] + sacc[ni][1];
        s2 += sacc[ni][2] + sacc[ni][3];
    }
    s1 += __shfl_xor_sync(0xffffffffu, s1, 1);
    s1 += __shfl_xor_sync(0xffffffffu, s1, 2);
    s2 += __shfl_xor_sync(0xffffffffu, s2, 1);
    s2 += __shfl_xor_sync(0xffffffffu, s2, 2);
    const float i1 = 1.f / s1, i2 = 1.f / s2;

#pragma unroll
    for (int ni = 0; ni < 8; ni++) {
        Qs[(m0 + g) * ASTW + ni * 4 + c]     = pack_h2(sacc[ni][0] * i1, sacc[ni][1] * i1);
        Qs[(m0 + g + 8) * ASTW + ni * 4 + c] = pack_h2(sacc[ni][2] * i2, sacc[ni][3] * i2);
    }
    __syncwarp();

    uint32_t preg[4][4];
#pragma unroll
    for (int ks = 0; ks < 4; ks++) {
        const uint32_t* pp = Qs + (m0 + g) * ASTW + ks * 8 + c;
        preg[ks][0] = pp[0];
        preg[ks][1] = pp[8 * ASTW];
        preg[ks][2] = pp[4];
        preg[ks][3] = pp[8 * ASTW + 4];
    }

    float oacc[8][4];
#pragma unroll
    for (int ni = 0; ni < 8; ni++)
#pragma unroll
        for (int e = 0; e < 4; e++) oacc[ni][e] = 0.f;

#pragma unroll
    for (int ni = 0; ni < 8; ni++) {
        const uint32_t* rowp = Vs + (ni * 8 + g) * ASTW;
#pragma unroll
        for (int ks = 0; ks < 4; ks++) {
            uint32_t bf[2];
            bf[0] = rowp[((((2 * ks)     ^ ni) & 7) << 2) + c];
            bf[1] = rowp[((((2 * ks + 1) ^ ni) & 7) << 2) + c];
            mma_f16(oacc[ni], preg[ks], bf);
        }
    }

    uint32_t* goh = (uint32_t*)g_oh;
    const size_t mrow1 = (size_t)win * 64 + m0 + g;
    const size_t mrow2 = mrow1 + 8;
#pragma unroll
    for (int ni = 0; ni < 8; ni++) {
        int d0 = h * 64 + ni * 8 + 2 * c;
        goh[(mrow1 * 512 + d0) >> 1] = pack_h2(oacc[ni][0], oacc[ni][1]);
        goh[(mrow2 * 512 + d0) >> 1] = pack_h2(oacc[ni][2], oacc[ni][3]);
    }
}

// ---------------------------------------------------------------------------
// Kernel 3: proj GEMM (fp16) + bias + unpartition/roll scatter.
//   M=131072 K=512 N=512
// ---------------------------------------------------------------------------
__global__ __launch_bounds__(256, 2) void k_proj_gemm(const float* __restrict__ bias,
                                                      float* __restrict__ out)
{
    extern __shared__ uint32_t sm32[];
    const uint32_t smemBase = (uint32_t)__cvta_generic_to_shared(sm32);

    const int tid   = threadIdx.x;
    const int nTile = blockIdx.x;
    const int mTile = blockIdx.y;

    const int warpId = tid >> 5, lane = tid & 31;
    const int warpM  = warpId & 3;
    const int warpN  = warpId >> 2;
    const int n0     = nTile * 128;
    const int g      = lane >> 2, t4 = lane & 3;

    float acc[2][8][4];
#pragma unroll
    for (int mi = 0; mi < 2; mi++)
#pragma unroll
        for (int ni = 0; ni < 8; ni++)
#pragma unroll
            for (int e = 0; e < 4; e++) acc[mi][ni][e] = 0.f;

    const __half* Ag = g_oh + (size_t)(mTile * 128) * 512;
    const __half* Bg = g_wph + (size_t)n0 * 512;
    GEMM_MAIN(Ag, Bg)

#pragma unroll
    for (int ni = 0; ni < 8; ni++) {
        int n  = n0 + warpN * 64 + ni * 8 + 2 * t4;
        float b0 = bias[n], b1 = bias[n + 1];
#pragma unroll
        for (int mi = 0; mi < 2; mi++) {
#pragma unroll
            for (int rr2 = 0; rr2 < 2; rr2++) {
                int m   = mTile * 128 + warpM * 32 + mi * 16 + g + rr2 * 8;
                int win = m >> 6, tt = m & 63;
                int b   = win >> 8;
                int wh  = (win >> 4) & 15;
                int ww  = win & 15;
                int ii  = tt >> 3, jj = tt & 7;
                int rO  = (wh * 8 + ii + 4) & 127;
                int cO  = (ww * 8 + jj + 4) & 127;
                size_t off = ((((size_t)b << 7) | rO) << 7 | cO) << 9;
                float2 v = make_float2(acc[mi][ni][rr2 * 2 + 0] + b0,
                                       acc[mi][ni][rr2 * 2 + 1] + b1);
                *(float2*)(out + off + n) = v;
            }
        }
    }
}

// ---------------------------------------------------------------------------
extern "C" void kernel_launch(void* const* d_in, const int* in_sizes, int n_in,
                              void* d_out, int out_size)
{
    const float* x      = (const float*)d_in[0];
    const float* qkv_w  = (const float*)d_in[1];
    const float* qkv_b  = (const float*)d_in[2];
    const float* proj_w = (const float*)d_in[3];
    const float* proj_b = (const float*)d_in[4];
    float* out = (float*)d_out;

    cudaFuncSetAttribute(k_qkv_gemm,  cudaFuncAttributeMaxDynamicSharedMemorySize, SMEM_BYTES);
    cudaFuncSetAttribute(k_proj_gemm, cudaFuncAttributeMaxDynamicSharedMemorySize, SMEM_BYTES);

    k_prep<<<16384 + 256, 256>>>(x, qkv_w, proj_w);
    k_qkv_gemm<<<dim3(12, 1024), 256, SMEM_BYTES>>>(qkv_b);
    k_attn_f16<<<2048 * 8, 128>>>();
    k_proj_gemm<<<dim3(4, 1024), 256, SMEM_BYTES>>>(proj_b, out);
}